// round 9
// baseline (speedup 1.0000x reference)
#include <cuda_runtime.h>
#include <cuda_fp16.h>
#include <cstdint>

#define CC 256
#define HWC 3136
#define MM 100352
#define NTILE 784
#define NTH 256
#define STRA 40                 /* halfs per smem row (80B, conflict-free ldmatrix) */
#define STG_AH 0
#define STG_AM 10240
#define STG_BH 20480
#define STG_BM 30720
#define STG_SZ 40960
#define SO_STG 8192
#define SO_FF  (SO_STG + 2*STG_SZ)        /* 90112: FFMA A stage (32KB) */
#define SO_FFB (SO_FF + 32768)            /* FFMA B stage (32KB) */
#define SMEM_T (SO_FFB + 32768)           /* 155648 */
#define INV2048 (1.0f/2048.0f)
typedef unsigned long long ull;

// -------------------- device scratch --------------------
__device__ __align__(16) float  g_buf[(size_t)CC*MM];
__device__ __align__(16) __half ut_hi_d[CC*CC], ut_mid_d[CC*CC];   // GEMM1 B [j][c]
__device__ __align__(16) __half w_hi_d[CC*CC],  w_mid_d[CC*CC];    // GEMM2 B [c][j] (u*iv split)
__device__ __align__(16) float  w_t_d[CC*CC];                      // GEMM2 B fp32 [j][c]
__device__ float    chsum_d[CC];
__device__ unsigned gmax_d[CC], gmin_d[CC];
__device__ float    mn_d[CC], s_d[CC], dmin_d[CC], scale_d[CC], inv_d[CC], cvv_d[CC];
__device__ float    qsum_d[CC], bias_d[CC], same_d[CC];

// -------------------- helpers --------------------
__device__ __forceinline__ ull pk(float lo, float hi) {
    ull r; asm("mov.b64 %0, {%1,%2};" : "=l"(r) : "f"(lo), "f"(hi)); return r;
}
__device__ __forceinline__ ull dup2(float v) { return pk(v, v); }
__device__ __forceinline__ void fma2(ull& d, ull a, ull b) {
    asm("fma.rn.f32x2 %0, %1, %2, %0;" : "+l"(d) : "l"(a), "l"(b));
}
__device__ __forceinline__ void upk(ull v, float& lo, float& hi) {
    asm("mov.b64 {%0,%1}, %2;" : "=f"(lo), "=f"(hi) : "l"(v));
}
__device__ __forceinline__ void cp16(uint32_t sdst, const void* g) {
    asm volatile("cp.async.ca.shared.global [%0], [%1], 16;" :: "r"(sdst), "l"(g) : "memory");
}
__device__ __forceinline__ void cp_commit() { asm volatile("cp.async.commit_group;" ::: "memory"); }
__device__ __forceinline__ void cp_wait0()  { asm volatile("cp.async.wait_group 0;" ::: "memory"); }

__device__ __forceinline__ void ldsm4(unsigned* r, uint32_t addr) {
    asm volatile("ldmatrix.sync.aligned.m8n8.x4.shared.b16 {%0,%1,%2,%3}, [%4];"
        : "=r"(r[0]), "=r"(r[1]), "=r"(r[2]), "=r"(r[3]) : "r"(addr));
}
__device__ __forceinline__ void mma16816(float* d, const unsigned* a, const unsigned* b) {
    asm volatile("mma.sync.aligned.m16n8k16.row.col.f32.f16.f16.f32 "
        "{%0,%1,%2,%3}, {%4,%5,%6,%7}, {%8,%9}, {%0,%1,%2,%3};"
        : "+f"(d[0]), "+f"(d[1]), "+f"(d[2]), "+f"(d[3])
        : "r"(a[0]), "r"(a[1]), "r"(a[2]), "r"(a[3]), "r"(b[0]), "r"(b[1]));
}
__device__ __forceinline__ unsigned encf(float f) {
    unsigned u = __float_as_uint(f);
    return (u & 0x80000000u) ? ~u : (u | 0x80000000u);
}
__device__ __forceinline__ float decf(unsigned u) {
    unsigned b = (u & 0x80000000u) ? (u & 0x7FFFFFFFu) : ~u;
    return __uint_as_float(b);
}
__device__ __forceinline__ float quant1(float g, float s, float dm, float sc, float iv,
                                        float cv, float sm) {
    float val = fminf(fmaxf(g - s, -cv), cv);
    float qq  = rintf((val - dm) * sc) * iv + dm;
    return (sm > 0.5f) ? val : qq;
}

// -------------------- prep: split u^T into fp16 hi/mid (scaled), zero accumulators ----
__global__ void prep_k(const float* __restrict__ u) {
    int t = threadIdx.x, b = blockIdx.x;
    if (b < CC) {
        float val = u[(size_t)b*CC + t];          // u[c=b][j=t]
        __half h = __float2half_rn(val);
        __half e = __float2half_rn((val - __half2float(h)) * 2048.0f);
        ut_hi_d[t*CC + b] = h;  ut_mid_d[t*CC + b] = e;   // [j][c] for GEMM1 B
    } else {
        chsum_d[t] = 0.0f; qsum_d[t] = 0.0f;
        gmax_d[t] = 0u; gmin_d[t] = 0xFFFFFFFFu;
    }
}

// -------------------- GEMM --------------------
// MODE 0: g[j][m] = sum_c relu(x[c,m]) * u[c][j]      (3-term split; +chsum, per-j max/min)
// MODE 1: out[c][m] = sum_j w[c][j]*n[j][m] + bias2[c]
//         HMMA for j 0..191 (2-term), exact FFMA2 side-channel for j 192..255.
template<int MODE>
__global__ void __launch_bounds__(NTH)
mgemm_k(const float* __restrict__ X, float* __restrict__ OUT)
{
    extern __shared__ char smem[];
    const uint32_t sb = (uint32_t)__cvta_generic_to_shared(smem);
    const int tid = threadIdx.x;
    const int lane = tid & 31, w = tid >> 5;
    const int m0 = blockIdx.x * 128;
    const int by = blockIdx.y;                 // n-half (0/1)
    const int NCH = MODE ? 6 : 8;              // HMMA chunk count

    float* ps = (float*)smem;                  // param arrays (MODE 1)
    if (MODE) {
        ps[tid]        = s_d[tid];
        ps[256 + tid]  = dmin_d[tid];
        ps[512 + tid]  = scale_d[tid];
        ps[768 + tid]  = cvv_d[tid];
        ps[1024 + tid] = bias_d[tid];
        __syncthreads();
        // FFMA stages: A = quant levels for j 192..255, B = w_t fp32
        float* As = (float*)(smem + SO_FF);
        float* Bs = (float*)(smem + SO_FFB);
        for (int idx = tid; idx < 8192; idx += NTH) {
            int j = idx >> 7, m = idx & 127;   // j local 0..63 -> global 192+j
            int c = 192 + j;
            float g = g_buf[(size_t)c*MM + m0 + m];
            float S = ps[c], DM = ps[256+c], SC = ps[512+c], CV = ps[768+c];
            float val = fminf(fmaxf(g - S, -CV), CV);
            As[idx] = rintf((val - DM) * SC);
            Bs[idx] = w_t_d[(size_t)c*CC + by*128 + m];
        }
    }

    const int mg = tid & 15, cp = tid >> 4;    // producer coords: 8-m group, k-pair
    const int mrow = m0 + mg*8;
    size_t abase = 0;
    if (!MODE) {
        int nimg = mrow / HWC;
        abase = (size_t)nimg*(CC*HWC) + (size_t)(mrow - nimg*HWC);
    }

    float v[2][8];

    auto loadA = [&](int kc) {
        #pragma unroll
        for (int cc = 0; cc < 2; cc++) {
            int c = kc*32 + cp*2 + cc;
            const float4* p;
            if (!MODE) p = (const float4*)(X + abase + (size_t)c*HWC);
            else       p = (const float4*)(g_buf + (size_t)c*MM + mrow);
            float4 q0 = p[0], q1 = p[1];
            v[cc][0]=q0.x; v[cc][1]=q0.y; v[cc][2]=q0.z; v[cc][3]=q0.w;
            v[cc][4]=q1.x; v[cc][5]=q1.y; v[cc][6]=q1.z; v[cc][7]=q1.w;
        }
    };
    auto procA = [&](int kc, int st) {
        char* base = smem + SO_STG + st*STG_SZ;
        #pragma unroll
        for (int cc = 0; cc < 2; cc++) {
            int c = kc*32 + cp*2 + cc;
            if (!MODE) {
                float s = 0.f;
                #pragma unroll
                for (int i = 0; i < 8; i++) { v[cc][i] = fmaxf(v[cc][i], 0.f); s += v[cc][i]; }
                s += __shfl_xor_sync(~0u, s, 1); s += __shfl_xor_sync(~0u, s, 2);
                s += __shfl_xor_sync(~0u, s, 4); s += __shfl_xor_sync(~0u, s, 8);
                if (by == 0 && (lane & 15) == 0) atomicAdd(&chsum_d[c], s);
            } else {
                float S=ps[c], DM=ps[256+c], SC=ps[512+c], CV=ps[768+c];
                #pragma unroll
                for (int i = 0; i < 8; i++) {
                    float val = fminf(fmaxf(v[cc][i] - S, -CV), CV);
                    v[cc][i] = rintf((val - DM) * SC);   // integer level, exact in fp16
                }
            }
        }
        if (!MODE) {
            #pragma unroll
            for (int i = 0; i < 8; i++) {
                __half h0 = __float2half_rn(v[0][i]);
                __half h1 = __float2half_rn(v[1][i]);
                __half e0 = __float2half_rn((v[0][i] - __half2float(h0)) * 2048.0f);
                __half e1 = __float2half_rn((v[1][i] - __half2float(h1)) * 2048.0f);
                uint32_t off = (uint32_t)(((mg*8 + i)*STRA + cp*2) * 2);
                *(__half2*)(base + STG_AH + off) = __halves2half2(h0, h1);
                *(__half2*)(base + STG_AM + off) = __halves2half2(e0, e1);
            }
        } else {
            #pragma unroll
            for (int i = 0; i < 8; i++) {
                uint32_t off = (uint32_t)(((mg*8 + i)*STRA + cp*2) * 2);
                *(__half2*)(base + STG_AH + off) =
                    __halves2half2(__float2half_rn(v[0][i]), __float2half_rn(v[1][i]));
            }
        }
    };
    auto prodB = [&](int kc, int st) {
        const __half* srch = MODE ? w_hi_d  : ut_hi_d;
        const __half* srcm = MODE ? w_mid_d : ut_mid_d;
        #pragma unroll
        for (int i = 0; i < 4; i++) {
            int ui = tid + i*NTH;                 // 0..1023
            int ish = (ui < 512);
            int r = (ui & 511) >> 2;              // row 0..127
            int q = ui & 3;
            uint32_t dst = sb + SO_STG + st*STG_SZ + (ish ? STG_BH : STG_BM)
                         + (uint32_t)(r*80 + q*16);
            const __half* s = (ish ? srch : srcm) + (size_t)(by*128 + r)*CC + kc*32 + q*8;
            cp16(dst, s);
        }
    };

    float acch[2][8][4] = {};
    float accm[2][8][4] = {};
    ull   facc[4][8];
    #pragma unroll
    for (int p = 0; p < 4; p++)
        #pragma unroll
        for (int q = 0; q < 8; q++) facc[p][q] = 0ull;

    const int wm = (w & 3) * 32;
    const int wn = (w >> 2) * 64;
    const int tm = (lane & 3) * 8;
    const int tn = (lane >> 2) * 8;

    prodB(0, 0); cp_commit();
    loadA(0);
    procA(0, 0);

    const int arow = (lane & 15);
    const int asel = (lane >> 4) << 3;
    const int brow = (lane & 7) + ((lane >> 4) << 3);
    const int bsel = ((lane >> 3) & 1) << 3;

    for (int kc = 0; kc < NCH; kc++) {
        const int st = kc & 1;
        if (kc < NCH - 1) loadA(kc + 1);
        cp_wait0();
        __syncthreads();

        const uint32_t ahb = sb + SO_STG + st*STG_SZ + STG_AH;
        const uint32_t bhb = sb + SO_STG + st*STG_SZ + STG_BH;
        #pragma unroll
        for (int ks = 0; ks < 2; ks++) {
            const int kb = ks*16;
            unsigned ah[2][4], am[2][4];
            #pragma unroll
            for (int mt = 0; mt < 2; mt++) {
                uint32_t ra = ahb + (uint32_t)(((wm + mt*16 + arow)*STRA + kb + asel) * 2);
                ldsm4(ah[mt], ra);
                if (!MODE) ldsm4(am[mt], ra + (STG_AM - STG_AH));
            }
            #pragma unroll
            for (int ng = 0; ng < 4; ng++) {
                uint32_t rb = bhb + (uint32_t)(((wn + ng*16 + brow)*STRA + kb + bsel) * 2);
                unsigned bh[4], bm[4];
                ldsm4(bh, rb);
                ldsm4(bm, rb + (STG_BM - STG_BH));
                #pragma unroll
                for (int mt = 0; mt < 2; mt++) {
                    if (!MODE) {
                        mma16816(acch[mt][ng*2],     ah[mt], bh);
                        mma16816(acch[mt][ng*2 + 1], ah[mt], bh + 2);
                        mma16816(accm[mt][ng*2],     ah[mt], bm);
                        mma16816(accm[mt][ng*2 + 1], ah[mt], bm + 2);
                        mma16816(accm[mt][ng*2],     am[mt], bh);
                        mma16816(accm[mt][ng*2 + 1], am[mt], bh + 2);
                    } else {
                        mma16816(acch[mt][ng*2],     ah[mt], bh);
                        mma16816(acch[mt][ng*2 + 1], ah[mt], bh + 2);
                        mma16816(acch[mt][ng*2],     ah[mt], bm);
                        mma16816(acch[mt][ng*2 + 1], ah[mt], bm + 2);
                    }
                }
            }
        }
        // ---- FFMA side-channel (MODE 1): 16 j per iteration, j 192..255 total ----
        if (MODE && kc < 4) {
            const float* As = (const float*)(smem + SO_FF);
            const float* Bs = (const float*)(smem + SO_FFB);
            #pragma unroll
            for (int jl = 0; jl < 16; jl++) {
                int j = kc*16 + jl;
                const float* ap = As + j*128 + wm + tm;
                ulonglong2 a01 = *(const ulonglong2*)(ap);
                ulonglong2 a23 = *(const ulonglong2*)(ap + 4);
                ull a[4] = { a01.x, a01.y, a23.x, a23.y };
                const float* bp = Bs + j*128 + wn + tn;
                float4 b0 = *(const float4*)(bp);
                float4 b1 = *(const float4*)(bp + 4);
                ull b[8] = { dup2(b0.x), dup2(b0.y), dup2(b0.z), dup2(b0.w),
                             dup2(b1.x), dup2(b1.y), dup2(b1.z), dup2(b1.w) };
                #pragma unroll
                for (int p = 0; p < 4; p++)
                    #pragma unroll
                    for (int q = 0; q < 8; q++)
                        fma2(facc[p][q], a[p], b[q]);
            }
        }
        if (kc < NCH - 1) { procA(kc + 1, st ^ 1); prodB(kc + 1, st ^ 1); cp_commit(); }
    }
    __syncthreads();   // stage buffers free -> reuse as transpose scratch

    float* scr = (float*)(smem + SO_STG) + w * (64*36);
    #pragma unroll
    for (int mt = 0; mt < 2; mt++)
        #pragma unroll
        for (int nt = 0; nt < 8; nt++)
            #pragma unroll
            for (int i = 0; i < 4; i++) {
                int nl = nt*8 + (lane & 3)*2 + (i & 1);
                int ml = mt*16 + (lane >> 2) + ((i >> 1) << 3);
                scr[nl*36 + ml] = MODE ? acch[mt][nt][i]
                                       : acch[mt][nt][i] + accm[mt][nt][i] * INV2048;
            }
    __syncwarp();
    if (MODE) {
        // merge exact-fp32 FFMA partials (j 192..255)
        #pragma unroll
        for (int p = 0; p < 4; p++)
            #pragma unroll
            for (int q = 0; q < 8; q++) {
                float lo, hi; upk(facc[p][q], lo, hi);
                float* d = scr + (tn + q)*36 + tm + 2*p;
                d[0] += lo; d[1] += hi;
            }
        __syncwarp();
    }

    if (!MODE) {
        #pragma unroll 4
        for (int r = 0; r < 64; r++) {
            int j = by*128 + wn + r;
            float val = scr[r*36 + lane];
            float mx = val, mn = val;
            #pragma unroll
            for (int d = 1; d < 32; d <<= 1) {
                mx = fmaxf(mx, __shfl_xor_sync(~0u, mx, d));
                mn = fminf(mn, __shfl_xor_sync(~0u, mn, d));
            }
            g_buf[(size_t)j*MM + m0 + wm + lane] = val;
            if (lane == 0) {
                atomicMax(&gmax_d[j], encf(mx));
                atomicMin(&gmin_d[j], encf(mn));
            }
        }
    } else {
        int mstart = m0 + wm;
        int nimg = mstart / HWC;
        size_t base = (size_t)nimg*(CC*HWC) + (size_t)(mstart - nimg*HWC);
        #pragma unroll 4
        for (int r = 0; r < 64; r++) {
            int c = by*128 + wn + r;
            OUT[base + (size_t)c*HWC + lane] = scr[r*36 + lane] + ps[1024 + c];
        }
    }
}

// -------------------- mid: mn, s, clip, quant params --------------------
__global__ void mid_k(const float* __restrict__ u, const float* __restrict__ cv,
                      const int* __restrict__ abw) {
    __shared__ float mns[CC];
    int t = threadIdx.x;
    float mn = chsum_d[t] * (1.0f / (float)MM);
    mn_d[t] = mn; mns[t] = mn;
    __syncthreads();
    float s = 0.0f;
    #pragma unroll 8
    for (int c = 0; c < CC; c++) s += u[(size_t)c*CC + t] * mns[c];
    s_d[t] = s;
    float c = cv[t]; cvv_d[t] = c;
    int ab = abw ? *abw : 8;
    float dmax = fminf(fmaxf(decf(gmax_d[t]) - s, -c), c);
    float dmin = fminf(fmaxf(decf(gmin_d[t]) - s, -c), c);
    int same = (dmax == dmin) || (ab >= 17);
    float rng = same ? 1.0f : (dmax - dmin);
    float levels = (float)((1 << (same ? 8 : ab)) - 1);
    same_d[t]  = same ? 1.0f : 0.0f;
    dmin_d[t]  = dmin;
    scale_d[t] = levels / rng;
    inv_d[t]   = rng / levels;
}

// -------------------- wsplit: w = u*iv fp16 hi/mid + fp32 transpose ----
__global__ void wsplit_k(const float* __restrict__ u) {
    int c = blockIdx.x, j = threadIdx.x;
    float wv = u[(size_t)c*CC + j] * inv_d[j];
    __half h = __float2half_rn(wv);
    __half e = __float2half_rn(wv - __half2float(h));
    w_hi_d [c*CC + j] = h;
    w_mid_d[c*CC + j] = e;
    w_t_d[(size_t)j*CC + c] = wv;
}

// -------------------- qsum: MLP-4 quant reduction --------------------
__global__ void __launch_bounds__(128) qsum_k() {
    __shared__ float red[4];
    int j = blockIdx.y;
    float s = s_d[j], dm = dmin_d[j], sc = scale_d[j], iv = inv_d[j],
          cv = cvv_d[j], smf = same_d[j];
    size_t base = (size_t)j*MM + (size_t)blockIdx.x*2048 + threadIdx.x*4;
    float4 v0 = *(const float4*)(g_buf + base);
    float4 v1 = *(const float4*)(g_buf + base + 512);
    float4 v2 = *(const float4*)(g_buf + base + 1024);
    float4 v3 = *(const float4*)(g_buf + base + 1536);
    float sum = quant1(v0.x,s,dm,sc,iv,cv,smf) + quant1(v0.y,s,dm,sc,iv,cv,smf)
              + quant1(v0.z,s,dm,sc,iv,cv,smf) + quant1(v0.w,s,dm,sc,iv,cv,smf)
              + quant1(v1.x,s,dm,sc,iv,cv,smf) + quant1(v1.y,s,dm,sc,iv,cv,smf)
              + quant1(v1.z,s,dm,sc,iv,cv,smf) + quant1(v1.w,s,dm,sc,iv,cv,smf)
              + quant1(v2.x,s,dm,sc,iv,cv,smf) + quant1(v2.y,s,dm,sc,iv,cv,smf)
              + quant1(v2.z,s,dm,sc,iv,cv,smf) + quant1(v2.w,s,dm,sc,iv,cv,smf)
              + quant1(v3.x,s,dm,sc,iv,cv,smf) + quant1(v3.y,s,dm,sc,iv,cv,smf)
              + quant1(v3.z,s,dm,sc,iv,cv,smf) + quant1(v3.w,s,dm,sc,iv,cv,smf);
    #pragma unroll
    for (int d = 1; d < 32; d <<= 1) sum += __shfl_xor_sync(~0u, sum, d);
    int lane = threadIdx.x & 31, wid = threadIdx.x >> 5;
    if (lane == 0) red[wid] = sum;
    __syncthreads();
    if (threadIdx.x == 0)
        atomicAdd(&qsum_d[j], red[0] + red[1] + red[2] + red[3]);
}

// -------------------- bias2[c] = mn[c] + sum_j u[c][j]*(dmin[j] - qmean[j]) ----
__global__ void bias_k(const float* __restrict__ u) {
    __shared__ float dq[CC];
    int t = threadIdx.x;
    dq[t] = dmin_d[t] - qsum_d[t] * (1.0f / (float)MM);
    __syncthreads();
    float b = 0.0f;
    #pragma unroll 8
    for (int j = 0; j < CC; j++) b += u[(size_t)t*CC + j] * dq[j];
    bias_d[t] = mn_d[t] + b;
}

// -------------------- launcher --------------------
extern "C" void kernel_launch(void* const* d_in, const int* in_sizes, int n_in,
                              void* d_out, int out_size) {
    const float* x  = (const float*)d_in[0];
    const float* u  = (const float*)d_in[1];
    const float* cv = (const float*)d_in[2];
    const int*   ab = (n_in > 3) ? (const int*)d_in[3] : nullptr;
    float* out = (float*)d_out;
    (void)in_sizes; (void)out_size;

    cudaFuncSetAttribute(mgemm_k<0>, cudaFuncAttributeMaxDynamicSharedMemorySize, SMEM_T);
    cudaFuncSetAttribute(mgemm_k<1>, cudaFuncAttributeMaxDynamicSharedMemorySize, SMEM_T);

    prep_k<<<CC + 1, CC>>>(u);
    mgemm_k<0><<<dim3(NTILE, 2), NTH, SMEM_T>>>(x, nullptr);
    mid_k<<<1, CC>>>(u, cv, ab);
    wsplit_k<<<CC, CC>>>(u);
    qsum_k<<<dim3(49, CC), 128>>>();
    bias_k<<<1, CC>>>(u);
    mgemm_k<1><<<dim3(NTILE, 2), NTH, SMEM_T>>>(nullptr, out);
}